// round 3
// baseline (speedup 1.0000x reference)
#include <cuda_runtime.h>
#include <math.h>

// Shapes (fixed by the problem)
#define BB 1024
#define TT 128
#define NN 256
#define HH 128
#define GG 512   // 4*H gate width
#define KK 384   // N + H combined reduction dim
#define BM 8     // batch rows per block in the recurrent kernel

// Scratch (no cudaMalloc allowed)
__device__ float g_a[BB * NN];      // softmax attention weights (time-invariant)
__device__ float g_wT[KK * GG];     // k-major combined weights: [k][j], k<256 -> w_ih, k>=256 -> w_hh
__device__ float g_bias[GG];        // b_ih + b_hh

// ---------------------------------------------------------------------------
// Setup: transpose weights into k-major layout, fold biases.
// ---------------------------------------------------------------------------
__global__ void setup_kernel(const float* __restrict__ w_ih,
                             const float* __restrict__ w_hh,
                             const float* __restrict__ b_ih,
                             const float* __restrict__ b_hh) {
    int idx = blockIdx.x * blockDim.x + threadIdx.x;
    if (idx < GG) g_bias[idx] = b_ih[idx] + b_hh[idx];
    int stride = gridDim.x * blockDim.x;
    for (int i = idx; i < KK * GG; i += stride) {
        int k = i >> 9;        // / 512
        int j = i & (GG - 1);  // % 512
        g_wT[i] = (k < NN) ? w_ih[j * NN + k] : w_hh[j * HH + (k - NN)];
    }
}

// ---------------------------------------------------------------------------
// Attention: feat[b,n] = sum_t x[b,t,n]*wx[t] + b; a = softmax_n(feat).
// softmax(feat + const_per_row) == softmax(feat), and the row constant
// (h@wh + c@wc) is the ONLY time-dependent term -> a is constant over t.
// One block per batch row, 256 threads (one per n).
// ---------------------------------------------------------------------------
__global__ __launch_bounds__(256)
void attn_kernel(const float* __restrict__ x,
                 const float* __restrict__ attn_w,
                 const float* __restrict__ attn_b,
                 float* __restrict__ out_attn) {
    __shared__ float s_wx[TT];
    __shared__ float s_red[256];
    int b = blockIdx.x;
    int n = threadIdx.x;
    if (n < TT) s_wx[n] = attn_w[2 * HH + n];  // wx = w[2H : 2H+T]
    __syncthreads();

    const float* xb = x + (size_t)b * TT * NN + n;
    float feat = attn_b[0];
#pragma unroll 8
    for (int t = 0; t < TT; t++) feat = fmaf(xb[(size_t)t * NN], s_wx[t], feat);

    // block softmax over 256 lanes
    s_red[n] = feat;
    __syncthreads();
#pragma unroll
    for (int s = 128; s > 0; s >>= 1) {
        if (n < s) s_red[n] = fmaxf(s_red[n], s_red[n + s]);
        __syncthreads();
    }
    float m = s_red[0];
    __syncthreads();
    float e = expf(feat - m);
    s_red[n] = e;
    __syncthreads();
#pragma unroll
    for (int s = 128; s > 0; s >>= 1) {
        if (n < s) s_red[n] += s_red[n + s];
        __syncthreads();
    }
    float a = e / s_red[0];

    g_a[b * NN + n] = a;

    // attentions output: same a broadcast to all T steps
    float* ob = out_attn + (size_t)b * TT * NN + n;
#pragma unroll 8
    for (int t = 0; t < TT; t++) ob[(size_t)t * NN] = a;
}

// ---------------------------------------------------------------------------
// Fused recurrent LSTM. 128 blocks x BM=8 batch rows. Each batch row's
// recurrence is independent -> no inter-block sync. 512 threads: thread tid
// owns gate column j = tid, accumulating over K=384 (wi part + h part) for
// all 8 local batch rows (8 FFMA per coalesced weight load; w stays in L2).
// ---------------------------------------------------------------------------
__device__ __forceinline__ float sigmoidf_(float v) {
    return 1.0f / (1.0f + expf(-v));
}

__global__ __launch_bounds__(512, 1)
void lstm_kernel(const float* __restrict__ x,
                 const float* __restrict__ h0,
                 const float* __restrict__ c0,
                 float* __restrict__ out_enc) {
    __shared__ float s_in[BM][KK];  // [r][0:256) = a*x_t, [r][256:384) = h
    __shared__ float s_a[BM][NN];   // attention weights for local rows
    __shared__ float s_c[BM][HH];   // cell state
    __shared__ float s_g[BM][GG];   // gate pre-activations

    int tid = threadIdx.x;
    int b0 = blockIdx.x * BM;

    // ---- init: a, h0, c0 into shared ----
    {
        int lin = tid * 4;
        int r = lin >> 8, n = lin & (NN - 1);
        *(float4*)&s_a[r][n] = *(const float4*)(g_a + (size_t)(b0 + r) * NN + n);
    }
    {
        int lin = tid * 2;
        int r = lin >> 7, k = lin & (HH - 1);
        *(float2*)&s_in[r][NN + k] = *(const float2*)(h0 + (size_t)(b0 + r) * HH + k);
        *(float2*)&s_c[r][k]       = *(const float2*)(c0 + (size_t)(b0 + r) * HH + k);
    }
    float bias = g_bias[tid];
    const float* wcol = g_wT + tid;
    __syncthreads();

    const int ur = (tid * 2) >> 7, uk = (tid * 2) & (HH - 1);   // update mapping
    const int wr = (tid * 4) >> 8, wn = (tid * 4) & (NN - 1);   // wi build mapping

    for (int t = 0; t < TT; t++) {
        // ---- build wi = a * x_t (coalesced global read) ----
        {
            float4 xv = *(const float4*)(x + ((size_t)(b0 + wr) * TT + t) * NN + wn);
            float4 av = *(const float4*)&s_a[wr][wn];
            float4 wv;
            wv.x = xv.x * av.x; wv.y = xv.y * av.y;
            wv.z = xv.z * av.z; wv.w = xv.w * av.w;
            *(float4*)&s_in[wr][wn] = wv;
        }
        __syncthreads();

        // ---- matvec: gates[r][tid] = bias + sum_k s_in[r][k] * wT[k][tid] ----
        float acc[BM];
#pragma unroll
        for (int r = 0; r < BM; r++) acc[r] = bias;
#pragma unroll 4
        for (int k = 0; k < KK; k++) {
            float w = wcol[(size_t)k * GG];   // coalesced; broadcast s_in via smem
#pragma unroll
            for (int r = 0; r < BM; r++) acc[r] = fmaf(s_in[r][k], w, acc[r]);
        }
#pragma unroll
        for (int r = 0; r < BM; r++) s_g[r][tid] = acc[r];
        __syncthreads();

        // ---- gate activations + state update (each thread owns 2 (r,k) cells) ----
        {
            float2 gi = *(const float2*)&s_g[ur][uk];
            float2 gf = *(const float2*)&s_g[ur][HH + uk];
            float2 gg = *(const float2*)&s_g[ur][2 * HH + uk];
            float2 go = *(const float2*)&s_g[ur][3 * HH + uk];
            float2 cc = *(const float2*)&s_c[ur][uk];

            float i0 = sigmoidf_(gi.x), i1 = sigmoidf_(gi.y);
            float f0 = sigmoidf_(gf.x), f1 = sigmoidf_(gf.y);
            float g0 = tanhf(gg.x),     g1 = tanhf(gg.y);
            float o0 = sigmoidf_(go.x), o1 = sigmoidf_(go.y);

            float c0n = fmaf(f0, cc.x, i0 * g0);
            float c1n = fmaf(f1, cc.y, i1 * g1);
            float h0n = o0 * tanhf(c0n);
            float h1n = o1 * tanhf(c1n);

            *(float2*)&s_c[ur][uk]        = make_float2(c0n, c1n);
            *(float2*)&s_in[ur][NN + uk]  = make_float2(h0n, h1n);
            *(float2*)(out_enc + ((size_t)(b0 + ur) * TT + t) * HH + uk) =
                make_float2(h0n, h1n);
        }
        __syncthreads();
    }
}

// ---------------------------------------------------------------------------
// Launch
// ---------------------------------------------------------------------------
extern "C" void kernel_launch(void* const* d_in, const int* in_sizes, int n_in,
                              void* d_out, int out_size) {
    const float* x      = (const float*)d_in[0];  // (B,T,N)
    const float* attn_w = (const float*)d_in[1];  // (1, 2H+T)
    const float* attn_b = (const float*)d_in[2];  // (1,)
    const float* w_ih   = (const float*)d_in[3];  // (4H, N)
    const float* w_hh   = (const float*)d_in[4];  // (4H, H)
    const float* b_ih   = (const float*)d_in[5];  // (4H,)
    const float* b_hh   = (const float*)d_in[6];  // (4H,)
    const float* h0     = (const float*)d_in[7];  // (B, H)
    const float* c0     = (const float*)d_in[8];  // (B, H)
    // d_in[9] = sample (unused)

    float* out      = (float*)d_out;
    float* out_attn = out;                          // (B,T,N)
    float* out_enc  = out + (size_t)BB * TT * NN;   // (B,T,H)

    setup_kernel<<<192, 256>>>(w_ih, w_hh, b_ih, b_hh);
    attn_kernel<<<BB, 256>>>(x, attn_w, attn_b, out_attn);
    lstm_kernel<<<BB / BM, 512>>>(x, h0, c0, out_enc);
}

// round 4
// speedup vs baseline: 1.9721x; 1.9721x over previous
#include <cuda_runtime.h>
#include <math.h>

#define BB 1024
#define TT 128
#define NN 256
#define HH 128
#define GG 512   // 4*H
#define BM 8     // batch rows per recurrent block

typedef unsigned long long ull;

// ---------------- scratch (__device__ globals; no cudaMalloc allowed) -------
__device__ float  g_a[BB * NN];            // softmax attention (time-invariant)
__device__ float  g_wB[NN * GG];           // k-major w_ih^T  [k][j]
__device__ float2 g_whh2[(HH / 2) * GG];   // pair-interleaved w_hh^T: [k2][j] = (w[2k2][j], w[2k2+1][j])
__device__ float  g_bias[GG];              // b_ih + b_hh
__device__ float  g_xproj[(size_t)BB * TT * GG];  // 268 MB: (a*x_t) @ w_ih^T

// ---------------- packed f32x2 helpers --------------------------------------
__device__ __forceinline__ ull pack2(float lo, float hi) {
    ull r; asm("mov.b64 %0, {%1,%2};" : "=l"(r) : "f"(lo), "f"(hi)); return r;
}
__device__ __forceinline__ void fma2(ull& d, ull a, ull b) {
    asm("fma.rn.f32x2 %0, %1, %2, %0;" : "+l"(d) : "l"(a), "l"(b));
}
__device__ __forceinline__ float2 unpack2(ull v) {
    float2 f; asm("mov.b64 {%0,%1}, %2;" : "=f"(f.x), "=f"(f.y) : "l"(v)); return f;
}

// ---------------------------------------------------------------------------
// Setup: k-major transposes + pair interleave + bias fold.
// ---------------------------------------------------------------------------
__global__ void setup_kernel(const float* __restrict__ w_ih,
                             const float* __restrict__ w_hh,
                             const float* __restrict__ b_ih,
                             const float* __restrict__ b_hh) {
    int idx = blockIdx.x * blockDim.x + threadIdx.x;
    int stride = gridDim.x * blockDim.x;
    if (idx < GG) g_bias[idx] = b_ih[idx] + b_hh[idx];
    for (int i = idx; i < NN * GG; i += stride) {
        int k = i >> 9, j = i & (GG - 1);
        g_wB[i] = w_ih[j * NN + k];
    }
    for (int i = idx; i < (HH / 2) * GG; i += stride) {
        int k2 = i >> 9, j = i & (GG - 1);
        g_whh2[i] = make_float2(w_hh[j * HH + 2 * k2], w_hh[j * HH + 2 * k2 + 1]);
    }
}

// ---------------------------------------------------------------------------
// Attention: a[b,:] = softmax_n( sum_t x[b,t,n]*wx[t] + b ).  The recurrent
// additive term (h@wh + c@wc) is a per-row constant -> softmax-invariant ->
// a is constant over t. Broadcast a into the attentions output.
// ---------------------------------------------------------------------------
__global__ __launch_bounds__(256)
void attn_kernel(const float* __restrict__ x,
                 const float* __restrict__ attn_w,
                 const float* __restrict__ attn_b,
                 float* __restrict__ out_attn) {
    __shared__ float s_wx[TT];
    __shared__ float s_red[256];
    int b = blockIdx.x;
    int n = threadIdx.x;
    if (n < TT) s_wx[n] = attn_w[2 * HH + n];
    __syncthreads();

    const float* xb = x + (size_t)b * TT * NN + n;
    float feat = attn_b[0];
#pragma unroll 8
    for (int t = 0; t < TT; t++) feat = fmaf(xb[(size_t)t * NN], s_wx[t], feat);

    s_red[n] = feat;
    __syncthreads();
#pragma unroll
    for (int s = 128; s > 0; s >>= 1) {
        if (n < s) s_red[n] = fmaxf(s_red[n], s_red[n + s]);
        __syncthreads();
    }
    float m = s_red[0];
    __syncthreads();
    float e = expf(feat - m);
    s_red[n] = e;
    __syncthreads();
#pragma unroll
    for (int s = 128; s > 0; s >>= 1) {
        if (n < s) s_red[n] += s_red[n + s];
        __syncthreads();
    }
    float a = e / s_red[0];

    g_a[b * NN + n] = a;

    float* ob = out_attn + (size_t)b * TT * NN + n;
#pragma unroll 8
    for (int t = 0; t < TT; t++) ob[(size_t)t * NN] = a;
}

// ---------------------------------------------------------------------------
// xproj GEMM: C[b][t][j] = sum_n (a[b][n]*x[b][t][n]) * w_ih[j][n]
// CTA = (jt, b): 128(t) x 128(j) tile, K = 256. 256 threads, 8x8 frag,
// f32x2-packed over j. As stored k-major [k][t] (LDA=132 to tame fill
// conflicts), Bs [k][128].
// ---------------------------------------------------------------------------
#define LDA 132
__global__ __launch_bounds__(256, 2)
void xproj_kernel(const float* __restrict__ x, float* __restrict__ xp) {
    __shared__ float As[32 * LDA];   // [k][t]
    __shared__ float Bs[32 * 128];   // [k][j]
    __shared__ float s_a[NN];

    int b = blockIdx.y, jt = blockIdx.x;
    int tid = threadIdx.x;
    int tx = tid & 15, ty = tid >> 4;     // frag: rows ty*8.., cols tx*8..
    const float* xb = x + (size_t)b * TT * NN;

    if (tid < 64) *(float4*)&s_a[tid * 4] = *(const float4*)&g_a[b * NN + tid * 4];

    ull acc[8][4];
#pragma unroll
    for (int i = 0; i < 8; i++)
#pragma unroll
        for (int jp = 0; jp < 4; jp++) acc[i][jp] = 0ULL;

    int tfill = tid >> 3;          // 0..31
    int kfill = (tid & 7) * 4;     // 0..28

    for (int kb = 0; kb < NN; kb += 32) {
        __syncthreads();
        // fill As[k][t] = x[t][kb+k] * a[kb+k]
#pragma unroll
        for (int it = 0; it < 4; it++) {
            int t = tfill + 32 * it;
            float4 xv = *(const float4*)&xb[t * NN + kb + kfill];
            As[(kfill + 0) * LDA + t] = xv.x * s_a[kb + kfill + 0];
            As[(kfill + 1) * LDA + t] = xv.y * s_a[kb + kfill + 1];
            As[(kfill + 2) * LDA + t] = xv.z * s_a[kb + kfill + 2];
            As[(kfill + 3) * LDA + t] = xv.w * s_a[kb + kfill + 3];
        }
        // fill Bs[k][j]
#pragma unroll
        for (int it = 0; it < 4; it++) {
            int i = tid + 256 * it;
            int k = i >> 5, j4 = (i & 31) * 4;
            *(float4*)&Bs[k * 128 + j4] =
                *(const float4*)&g_wB[(size_t)(kb + k) * GG + jt * 128 + j4];
        }
        __syncthreads();

#pragma unroll
        for (int k = 0; k < 32; k++) {
            float4 av0 = *(const float4*)&As[k * LDA + ty * 8];
            float4 av1 = *(const float4*)&As[k * LDA + ty * 8 + 4];
            ull a2[8];
            a2[0] = pack2(av0.x, av0.x); a2[1] = pack2(av0.y, av0.y);
            a2[2] = pack2(av0.z, av0.z); a2[3] = pack2(av0.w, av0.w);
            a2[4] = pack2(av1.x, av1.x); a2[5] = pack2(av1.y, av1.y);
            a2[6] = pack2(av1.z, av1.z); a2[7] = pack2(av1.w, av1.w);
            ulonglong2 b01 = *(const ulonglong2*)&Bs[k * 128 + tx * 8];
            ulonglong2 b23 = *(const ulonglong2*)&Bs[k * 128 + tx * 8 + 4];
#pragma unroll
            for (int i = 0; i < 8; i++) {
                fma2(acc[i][0], a2[i], b01.x);
                fma2(acc[i][1], a2[i], b01.y);
                fma2(acc[i][2], a2[i], b23.x);
                fma2(acc[i][3], a2[i], b23.y);
            }
        }
    }

#pragma unroll
    for (int i = 0; i < 8; i++) {
        int t = ty * 8 + i;
        ull* o = (ull*)(xp + ((size_t)b * TT + t) * GG + jt * 128 + tx * 8);
        o[0] = acc[i][0]; o[1] = acc[i][1]; o[2] = acc[i][2]; o[3] = acc[i][3];
    }
}

// ---------------------------------------------------------------------------
// Recurrent LSTM: only h @ w_hh^T (K=128) per step; xproj precomputed.
// 128 blocks x 8 batch rows, 256 threads; thread owns j0=tid, j1=tid+256
// (f32x2-packed over k). First 96 k-rows of w_hh^T cached in 192KB smem.
// ---------------------------------------------------------------------------
#define WS_K2 48      // k2 rows cached in smem (k < 96)
#define WS_F4 ((WS_K2 * GG * 2) / 4)   // float4 count = 12288

__device__ __forceinline__ float sigmoidf_(float v) {
    return 1.0f / (1.0f + expf(-v));
}

__global__ __launch_bounds__(256, 1)
void lstm_kernel(const float* __restrict__ xp,
                 const float* __restrict__ h0,
                 const float* __restrict__ c0,
                 float* __restrict__ out_enc) {
    extern __shared__ char smem_raw[];
    float2* ws  = (float2*)smem_raw;                        // [WS_K2][GG]
    float*  s_h = (float*)(smem_raw + WS_K2 * GG * 8);      // [BM][HH]
    float*  s_c = s_h + BM * HH;                            // [BM][HH]
    float*  s_g = s_c + BM * HH;                            // [BM][GG]

    int tid = threadIdx.x;
    int b0 = blockIdx.x * BM;

    // cache 3/4 of w_hh^T pairs in smem
    for (int i = tid; i < WS_F4; i += 256)
        ((float4*)ws)[i] = ((const float4*)g_whh2)[i];

    // init h, c
    {
        int lin = tid * 4;
        int r = lin >> 7, k = lin & (HH - 1);
        *(float4*)&s_h[r * HH + k] = *(const float4*)&h0[(size_t)(b0 + r) * HH + k];
        *(float4*)&s_c[r * HH + k] = *(const float4*)&c0[(size_t)(b0 + r) * HH + k];
    }
    int j0 = tid, j1 = tid + 256;
    float bias0 = g_bias[j0], bias1 = g_bias[j1];
    __syncthreads();

    const int ur = tid >> 5, uk = (tid & 31) * 4;

    for (int t = 0; t < TT; t++) {
        // prefetch xproj (consumed ~4K cycles later)
        float xpv0[BM], xpv1[BM];
#pragma unroll
        for (int r = 0; r < BM; r++) {
            const float* row = xp + ((size_t)(b0 + r) * TT + t) * GG;
            xpv0[r] = row[j0];
            xpv1[r] = row[j1];
        }

        ull acc0[BM], acc1[BM];
#pragma unroll
        for (int r = 0; r < BM; r++) { acc0[r] = 0ULL; acc1[r] = 0ULL; }

        // uncached tail first (k = 96..127), LDG from L2
#pragma unroll 4
        for (int k4 = 24; k4 < 32; k4++) {
            ull w00 = *(const ull*)&g_whh2[(2 * k4) * GG + j0];
            ull w01 = *(const ull*)&g_whh2[(2 * k4 + 1) * GG + j0];
            ull w10 = *(const ull*)&g_whh2[(2 * k4) * GG + j1];
            ull w11 = *(const ull*)&g_whh2[(2 * k4 + 1) * GG + j1];
#pragma unroll
            for (int r = 0; r < BM; r++) {
                ulonglong2 hp = *(const ulonglong2*)&s_h[r * HH + 4 * k4];
                fma2(acc0[r], hp.x, w00); fma2(acc0[r], hp.y, w01);
                fma2(acc1[r], hp.x, w10); fma2(acc1[r], hp.y, w11);
            }
        }
        // cached body (k = 0..95), LDS
#pragma unroll 4
        for (int k4 = 0; k4 < 24; k4++) {
            ull w00 = *(const ull*)&ws[(2 * k4) * GG + j0];
            ull w01 = *(const ull*)&ws[(2 * k4 + 1) * GG + j0];
            ull w10 = *(const ull*)&ws[(2 * k4) * GG + j1];
            ull w11 = *(const ull*)&ws[(2 * k4 + 1) * GG + j1];
#pragma unroll
            for (int r = 0; r < BM; r++) {
                ulonglong2 hp = *(const ulonglong2*)&s_h[r * HH + 4 * k4];
                fma2(acc0[r], hp.x, w00); fma2(acc0[r], hp.y, w01);
                fma2(acc1[r], hp.x, w10); fma2(acc1[r], hp.y, w11);
            }
        }

#pragma unroll
        for (int r = 0; r < BM; r++) {
            float2 p0 = unpack2(acc0[r]);
            float2 p1 = unpack2(acc1[r]);
            s_g[r * GG + j0] = p0.x + p0.y + bias0 + xpv0[r];
            s_g[r * GG + j1] = p1.x + p1.y + bias1 + xpv1[r];
        }
        __syncthreads();

        // gate activations + state update: thread owns (ur, uk..uk+3)
        {
            float4 gi = *(const float4*)&s_g[ur * GG + uk];
            float4 gf = *(const float4*)&s_g[ur * GG + HH + uk];
            float4 gg = *(const float4*)&s_g[ur * GG + 2 * HH + uk];
            float4 go = *(const float4*)&s_g[ur * GG + 3 * HH + uk];
            float4 cc = *(const float4*)&s_c[ur * HH + uk];

            float gI[4] = {gi.x, gi.y, gi.z, gi.w};
            float gF[4] = {gf.x, gf.y, gf.z, gf.w};
            float gGv[4] = {gg.x, gg.y, gg.z, gg.w};
            float gO[4] = {go.x, go.y, go.z, go.w};
            float cC[4] = {cc.x, cc.y, cc.z, cc.w};
            float hn[4], cn[4];
#pragma unroll
            for (int l = 0; l < 4; l++) {
                float iv = sigmoidf_(gI[l]);
                float fv = sigmoidf_(gF[l]);
                float gv = tanhf(gGv[l]);
                float ov = sigmoidf_(gO[l]);
                cn[l] = fmaf(fv, cC[l], iv * gv);
                hn[l] = ov * tanhf(cn[l]);
            }
            *(float4*)&s_c[ur * HH + uk] = make_float4(cn[0], cn[1], cn[2], cn[3]);
            *(float4*)&s_h[ur * HH + uk] = make_float4(hn[0], hn[1], hn[2], hn[3]);
            *(float4*)(out_enc + ((size_t)(b0 + ur) * TT + t) * HH + uk) =
                make_float4(hn[0], hn[1], hn[2], hn[3]);
        }
        __syncthreads();
    }
}

// ---------------------------------------------------------------------------
// Launch
// ---------------------------------------------------------------------------
extern "C" void kernel_launch(void* const* d_in, const int* in_sizes, int n_in,
                              void* d_out, int out_size) {
    const float* x      = (const float*)d_in[0];
    const float* attn_w = (const float*)d_in[1];
    const float* attn_b = (const float*)d_in[2];
    const float* w_ih   = (const float*)d_in[3];
    const float* w_hh   = (const float*)d_in[4];
    const float* b_ih   = (const float*)d_in[5];
    const float* b_hh   = (const float*)d_in[6];
    const float* h0     = (const float*)d_in[7];
    const float* c0     = (const float*)d_in[8];

    float* out      = (float*)d_out;
    float* out_attn = out;                         // (B,T,N)
    float* out_enc  = out + (size_t)BB * TT * NN;  // (B,T,H)

    float* xproj;
    cudaGetSymbolAddress((void**)&xproj, g_xproj);

    static bool attr_set = false;
    int lstm_smem = WS_K2 * GG * 8 + BM * HH * 4 * 2 + BM * GG * 4;  // 221184 B
    if (!attr_set) {
        cudaFuncSetAttribute(lstm_kernel,
                             cudaFuncAttributeMaxDynamicSharedMemorySize, lstm_smem);
        attr_set = true;
    }

    setup_kernel<<<192, 256>>>(w_ih, w_hh, b_ih, b_hh);
    attn_kernel<<<BB, 256>>>(x, attn_w, attn_b, out_attn);
    xproj_kernel<<<dim3(4, BB), 256>>>(x, xproj);
    lstm_kernel<<<BB / BM, 256, lstm_smem>>>(xproj, h0, c0, out_enc);
}

// round 5
// speedup vs baseline: 2.1081x; 1.0690x over previous
#include <cuda_runtime.h>
#include <math.h>

#define BB 1024
#define TT 128
#define NN 256
#define HH 128
#define GG 512    // 4*H
#define BM 7      // batch rows per recurrent block
#define NBLK 147  // ceil(1024/7) -> 147*7 = 1029 (5 pad rows, guarded)
#define SM_K4 24  // k4 groups (4 k each) of w_hh^T cached in smem (k < 96)

typedef unsigned long long ull;

// ---------------- scratch (__device__ globals; no cudaMalloc allowed) -------
__device__ float  g_a[BB * NN];           // softmax attention (time-invariant)
__device__ float  g_wB[NN * GG];          // k-major w_ih^T  [k][j]
__device__ float4 g_whh4[32 * GG];        // [k4][j] = w_hh^T[4k4..4k4+3][j]
__device__ float  g_bias[GG];             // b_ih + b_hh
__device__ float  g_xproj[(size_t)BB * TT * GG];  // (a*x_t) @ w_ih^T

// ---------------- packed f32x2 helpers --------------------------------------
__device__ __forceinline__ ull pack2(float lo, float hi) {
    ull r; asm("mov.b64 %0, {%1,%2};" : "=l"(r) : "f"(lo), "f"(hi)); return r;
}
__device__ __forceinline__ void fma2(ull& d, ull a, ull b) {
    asm("fma.rn.f32x2 %0, %1, %2, %0;" : "+l"(d) : "l"(a), "l"(b));
}
__device__ __forceinline__ float2 unpack2(ull v) {
    float2 f; asm("mov.b64 {%0,%1}, %2;" : "=f"(f.x), "=f"(f.y) : "l"(v)); return f;
}

__device__ __forceinline__ float fsig(float x) {
    float e = __expf(-x);
    return __fdividef(1.0f, 1.0f + e);
}
__device__ __forceinline__ float ftanh(float x) {
    float e = __expf(2.0f * x);
    return 1.0f - __fdividef(2.0f, e + 1.0f);
}

// ---------------------------------------------------------------------------
// Setup: k-major transposes + 4-k interleave + bias fold.
// ---------------------------------------------------------------------------
__global__ void setup_kernel(const float* __restrict__ w_ih,
                             const float* __restrict__ w_hh,
                             const float* __restrict__ b_ih,
                             const float* __restrict__ b_hh) {
    int idx = blockIdx.x * blockDim.x + threadIdx.x;
    int stride = gridDim.x * blockDim.x;
    if (idx < GG) g_bias[idx] = b_ih[idx] + b_hh[idx];
    for (int i = idx; i < NN * GG; i += stride) {
        int k = i >> 9, j = i & (GG - 1);
        g_wB[i] = w_ih[j * NN + k];
    }
    for (int i = idx; i < 32 * GG; i += stride) {
        int k4 = i >> 9, j = i & (GG - 1);
        const float* wr = w_hh + j * HH + 4 * k4;
        g_whh4[i] = make_float4(wr[0], wr[1], wr[2], wr[3]);
    }
}

// ---------------------------------------------------------------------------
// Attention: a[b,:] = softmax_n( sum_t x[b,t,n]*wx[t] + b ).  The recurrent
// additive term (h@wh + c@wc) is a per-row constant -> softmax-invariant ->
// a is constant over t. Broadcast a into the attentions output.
// ---------------------------------------------------------------------------
__global__ __launch_bounds__(256)
void attn_kernel(const float* __restrict__ x,
                 const float* __restrict__ attn_w,
                 const float* __restrict__ attn_b,
                 float* __restrict__ out_attn) {
    __shared__ float s_wx[TT];
    __shared__ float s_red[256];
    int b = blockIdx.x;
    int n = threadIdx.x;
    if (n < TT) s_wx[n] = attn_w[2 * HH + n];
    __syncthreads();

    const float* xb = x + (size_t)b * TT * NN + n;
    float feat = attn_b[0];
#pragma unroll 8
    for (int t = 0; t < TT; t++) feat = fmaf(xb[(size_t)t * NN], s_wx[t], feat);

    s_red[n] = feat;
    __syncthreads();
#pragma unroll
    for (int s = 128; s > 0; s >>= 1) {
        if (n < s) s_red[n] = fmaxf(s_red[n], s_red[n + s]);
        __syncthreads();
    }
    float m = s_red[0];
    __syncthreads();
    float e = expf(feat - m);
    s_red[n] = e;
    __syncthreads();
#pragma unroll
    for (int s = 128; s > 0; s >>= 1) {
        if (n < s) s_red[n] += s_red[n + s];
        __syncthreads();
    }
    float a = e / s_red[0];

    g_a[b * NN + n] = a;

    float* ob = out_attn + (size_t)b * TT * NN + n;
#pragma unroll 8
    for (int t = 0; t < TT; t++) ob[(size_t)t * NN] = a;
}

// ---------------------------------------------------------------------------
// xproj GEMM: C[b][t][j] = sum_n (a[b][n]*x[b][t][n]) * w_ih[j][n]
// CTA = (jt, b): 128(t) x 128(j) tile, K = 256. 256 threads, 8x8 frag,
// f32x2-packed over j.
// ---------------------------------------------------------------------------
#define LDA 132
__global__ __launch_bounds__(256, 2)
void xproj_kernel(const float* __restrict__ x, float* __restrict__ xp) {
    __shared__ float As[32 * LDA];   // [k][t]
    __shared__ float Bs[32 * 128];   // [k][j]
    __shared__ float s_a[NN];

    int b = blockIdx.y, jt = blockIdx.x;
    int tid = threadIdx.x;
    int tx = tid & 15, ty = tid >> 4;
    const float* xb = x + (size_t)b * TT * NN;

    if (tid < 64) *(float4*)&s_a[tid * 4] = *(const float4*)&g_a[b * NN + tid * 4];

    ull acc[8][4];
#pragma unroll
    for (int i = 0; i < 8; i++)
#pragma unroll
        for (int jp = 0; jp < 4; jp++) acc[i][jp] = 0ULL;

    int tfill = tid >> 3;
    int kfill = (tid & 7) * 4;

    for (int kb = 0; kb < NN; kb += 32) {
        __syncthreads();
#pragma unroll
        for (int it = 0; it < 4; it++) {
            int t = tfill + 32 * it;
            float4 xv = *(const float4*)&xb[t * NN + kb + kfill];
            As[(kfill + 0) * LDA + t] = xv.x * s_a[kb + kfill + 0];
            As[(kfill + 1) * LDA + t] = xv.y * s_a[kb + kfill + 1];
            As[(kfill + 2) * LDA + t] = xv.z * s_a[kb + kfill + 2];
            As[(kfill + 3) * LDA + t] = xv.w * s_a[kb + kfill + 3];
        }
#pragma unroll
        for (int it = 0; it < 4; it++) {
            int i = tid + 256 * it;
            int k = i >> 5, j4 = (i & 31) * 4;
            *(float4*)&Bs[k * 128 + j4] =
                *(const float4*)&g_wB[(size_t)(kb + k) * GG + jt * 128 + j4];
        }
        __syncthreads();

#pragma unroll
        for (int k = 0; k < 32; k++) {
            float4 av0 = *(const float4*)&As[k * LDA + ty * 8];
            float4 av1 = *(const float4*)&As[k * LDA + ty * 8 + 4];
            ull a2[8];
            a2[0] = pack2(av0.x, av0.x); a2[1] = pack2(av0.y, av0.y);
            a2[2] = pack2(av0.z, av0.z); a2[3] = pack2(av0.w, av0.w);
            a2[4] = pack2(av1.x, av1.x); a2[5] = pack2(av1.y, av1.y);
            a2[6] = pack2(av1.z, av1.z); a2[7] = pack2(av1.w, av1.w);
            ulonglong2 b01 = *(const ulonglong2*)&Bs[k * 128 + tx * 8];
            ulonglong2 b23 = *(const ulonglong2*)&Bs[k * 128 + tx * 8 + 4];
#pragma unroll
            for (int i = 0; i < 8; i++) {
                fma2(acc[i][0], a2[i], b01.x);
                fma2(acc[i][1], a2[i], b01.y);
                fma2(acc[i][2], a2[i], b23.x);
                fma2(acc[i][3], a2[i], b23.y);
            }
        }
    }

#pragma unroll
    for (int i = 0; i < 8; i++) {
        int t = ty * 8 + i;
        ull* o = (ull*)(xp + ((size_t)b * TT + t) * GG + jt * 128 + tx * 8);
        o[0] = acc[i][0]; o[1] = acc[i][1]; o[2] = acc[i][2]; o[3] = acc[i][3];
    }
}

// ---------------------------------------------------------------------------
// Recurrent LSTM: gates = xproj[t] + h @ w_hh^T (K=128 only) per step.
// 147 blocks x 7 batch rows, 512 threads; thread owns one gate column j.
// k<96 weights in smem (float4 per (k4,j) -> one LDS.128), k>=96 weights
// held in registers across all 128 steps. h broadcast via smem (free).
// ---------------------------------------------------------------------------
__global__ __launch_bounds__(512, 1)
void lstm_kernel(const float* __restrict__ xp,
                 const float* __restrict__ h0,
                 const float* __restrict__ c0,
                 float* __restrict__ out_enc) {
    extern __shared__ char smem_raw[];
    float4* ws  = (float4*)smem_raw;                         // [SM_K4][GG]
    float*  s_h = (float*)(smem_raw + SM_K4 * GG * 16);      // [BM][HH]
    float*  s_c = s_h + BM * HH;                             // [BM][HH]
    float*  s_g = s_c + BM * HH;                             // [BM][GG]

    int tid = threadIdx.x;
    int b0 = blockIdx.x * BM;
    int j = tid;

    // cache k<96 weights in smem
    for (int i = tid; i < SM_K4 * GG; i += 512) ws[i] = g_whh4[i];

    // tail weights (k = 96..127) in registers, reused for all 128 steps
    ulonglong2 wt[8];
#pragma unroll
    for (int q = 0; q < 8; q++)
        wt[q] = *(const ulonglong2*)&g_whh4[(SM_K4 + q) * GG + j];

    // init h, c (pad rows -> 0)
    for (int i = tid; i < BM * HH; i += 512) {
        int r = i >> 7, k = i & (HH - 1);
        int b = b0 + r;
        float hv = 0.f, cv = 0.f;
        if (b < BB) { hv = h0[(size_t)b * HH + k]; cv = c0[(size_t)b * HH + k]; }
        s_h[i] = hv; s_c[i] = cv;
    }
    float bias = g_bias[j];
    __syncthreads();

    // per-row xproj pointers (clamped for pad rows; reads harmless)
    const float* xrow[BM];
#pragma unroll
    for (int r = 0; r < BM; r++) {
        int b = b0 + r; if (b > BB - 1) b = BB - 1;
        xrow[r] = xp + (size_t)b * TT * GG + j;
    }

    const float4* wsj = ws + j;
    const int lin = tid * 2;
    const int er = lin >> 7, ek = lin & (HH - 1);
    const bool eact = lin < BM * HH;
    const bool ewr  = eact && (b0 + er < BB);

    for (int t = 0; t < TT; t++) {
        // prefetch xproj for this step (consumed only after the matvec)
        float xpv[BM];
#pragma unroll
        for (int r = 0; r < BM; r++) xpv[r] = xrow[r][(size_t)t * GG];

        ull acc[BM];
#pragma unroll
        for (int r = 0; r < BM; r++) acc[r] = 0ULL;

#pragma unroll
        for (int k4 = 0; k4 < SM_K4; k4++) {
            ulonglong2 wp = *(const ulonglong2*)&wsj[k4 * GG];
#pragma unroll
            for (int r = 0; r < BM; r++) {
                ulonglong2 hp = *(const ulonglong2*)&s_h[r * HH + k4 * 4];
                fma2(acc[r], hp.x, wp.x);
                fma2(acc[r], hp.y, wp.y);
            }
        }
#pragma unroll
        for (int q = 0; q < 8; q++) {
#pragma unroll
            for (int r = 0; r < BM; r++) {
                ulonglong2 hp = *(const ulonglong2*)&s_h[r * HH + (SM_K4 + q) * 4];
                fma2(acc[r], hp.x, wt[q].x);
                fma2(acc[r], hp.y, wt[q].y);
            }
        }

#pragma unroll
        for (int r = 0; r < BM; r++) {
            float2 p = unpack2(acc[r]);
            s_g[r * GG + j] = p.x + p.y + bias + xpv[r];
        }
        __syncthreads();

        // gate activations + state update: thread owns cells (er, ek..ek+1)
        if (eact) {
            float2 gi = *(const float2*)&s_g[er * GG + ek];
            float2 gf = *(const float2*)&s_g[er * GG + HH + ek];
            float2 gg = *(const float2*)&s_g[er * GG + 2 * HH + ek];
            float2 go = *(const float2*)&s_g[er * GG + 3 * HH + ek];
            float2 cc = *(const float2*)&s_c[er * HH + ek];

            float i0 = fsig(gi.x), i1 = fsig(gi.y);
            float f0 = fsig(gf.x), f1 = fsig(gf.y);
            float g0 = ftanh(gg.x), g1 = ftanh(gg.y);
            float o0 = fsig(go.x), o1 = fsig(go.y);

            float c0n = fmaf(f0, cc.x, i0 * g0);
            float c1n = fmaf(f1, cc.y, i1 * g1);
            float h0n = o0 * ftanh(c0n);
            float h1n = o1 * ftanh(c1n);

            *(float2*)&s_c[er * HH + ek] = make_float2(c0n, c1n);
            *(float2*)&s_h[er * HH + ek] = make_float2(h0n, h1n);
            if (ewr)
                *(float2*)(out_enc + ((size_t)(b0 + er) * TT + t) * HH + ek) =
                    make_float2(h0n, h1n);
        }
        __syncthreads();
    }
}

// ---------------------------------------------------------------------------
// Launch
// ---------------------------------------------------------------------------
extern "C" void kernel_launch(void* const* d_in, const int* in_sizes, int n_in,
                              void* d_out, int out_size) {
    const float* x      = (const float*)d_in[0];
    const float* attn_w = (const float*)d_in[1];
    const float* attn_b = (const float*)d_in[2];
    const float* w_ih   = (const float*)d_in[3];
    const float* w_hh   = (const float*)d_in[4];
    const float* b_ih   = (const float*)d_in[5];
    const float* b_hh   = (const float*)d_in[6];
    const float* h0     = (const float*)d_in[7];
    const float* c0     = (const float*)d_in[8];

    float* out      = (float*)d_out;
    float* out_attn = out;                         // (B,T,N)
    float* out_enc  = out + (size_t)BB * TT * NN;  // (B,T,H)

    float* xproj;
    cudaGetSymbolAddress((void**)&xproj, g_xproj);

    int lstm_smem = SM_K4 * GG * 16 + BM * HH * 4 * 2 + BM * GG * 4;  // 218112
    static bool attr_set = false;
    if (!attr_set) {
        cudaFuncSetAttribute(lstm_kernel,
                             cudaFuncAttributeMaxDynamicSharedMemorySize, lstm_smem);
        attr_set = true;
    }

    setup_kernel<<<192, 256>>>(w_ih, w_hh, b_ih, b_hh);
    attn_kernel<<<BB, 256>>>(x, attn_w, attn_b, out_attn);
    xproj_kernel<<<dim3(4, BB), 256>>>(x, xproj);
    lstm_kernel<<<NBLK, 512, lstm_smem>>>(xproj, h0, c0, out_enc);
}

// round 7
// speedup vs baseline: 2.5882x; 1.2278x over previous
#include <cuda_runtime.h>
#include <cuda_bf16.h>
#include <mma.h>
#include <math.h>

using namespace nvcuda;

#define BB 1024
#define TT 128
#define NN 256
#define HH 128
#define GG 512
#define BM 7
#define NBLK 147
#define SM_K4 24
#define KP 768          // concatenated K' = 3*256 (hi|lo|hi)
#define AP 528          // A smem row pitch (bf16 elems)
#define BP 72           // B smem column pitch (bf16 elems)

typedef unsigned long long ull;
typedef unsigned int u32;

// ---------------- scratch ----------------------------------------------------
__device__ float  g_a[BB * NN];
__device__ float4 g_whh4[32 * GG];
__device__ float  g_bias[GG];
__device__ float  g_xproj[(size_t)BB * TT * GG];
__device__ __nv_bfloat16 g_wcat[GG * KP];   // [j][k'] : k'<256 hi, <512 lo, <768 hi

// ---------------- f32x2 helpers ----------------------------------------------
__device__ __forceinline__ void fma2(ull& d, ull a, ull b) {
    asm("fma.rn.f32x2 %0, %1, %2, %0;" : "+l"(d) : "l"(a), "l"(b));
}
__device__ __forceinline__ float2 unpack2(ull v) {
    float2 f; asm("mov.b64 {%0,%1}, %2;" : "=f"(f.x), "=f"(f.y) : "l"(v)); return f;
}
__device__ __forceinline__ float fsig(float x) {
    float e = __expf(-x); return __fdividef(1.0f, 1.0f + e);
}
__device__ __forceinline__ float ftanh(float x) {
    float e = __expf(2.0f * x); return 1.0f - __fdividef(2.0f, e + 1.0f);
}

// ---------------------------------------------------------------------------
// Setup: lstm weight interleave + bias fold + bf16 split-concat of w_ih.
// ---------------------------------------------------------------------------
__global__ void setup_kernel(const float* __restrict__ w_ih,
                             const float* __restrict__ w_hh,
                             const float* __restrict__ b_ih,
                             const float* __restrict__ b_hh) {
    int idx = blockIdx.x * blockDim.x + threadIdx.x;
    int stride = gridDim.x * blockDim.x;
    if (idx < GG) g_bias[idx] = b_ih[idx] + b_hh[idx];
    for (int i = idx; i < 32 * GG; i += stride) {
        int k4 = i >> 9, j = i & (GG - 1);
        const float* wr = w_hh + j * HH + 4 * k4;
        g_whh4[i] = make_float4(wr[0], wr[1], wr[2], wr[3]);
    }
    for (int i = idx; i < GG * KP; i += stride) {
        int j = i / KP, kp = i % KP;
        int k = kp & 255;
        float v = w_ih[j * NN + k];
        __nv_bfloat16 hi = __float2bfloat16_rn(v);
        __nv_bfloat16 outv;
        if (kp < 256)       outv = hi;
        else if (kp < 512)  outv = __float2bfloat16_rn(v - __bfloat162float(hi));
        else                outv = hi;
        g_wcat[i] = outv;
    }
}

// ---------------------------------------------------------------------------
// Attention (time-invariant softmax) — unchanged.
// ---------------------------------------------------------------------------
__global__ __launch_bounds__(256)
void attn_kernel(const float* __restrict__ x,
                 const float* __restrict__ attn_w,
                 const float* __restrict__ attn_b,
                 float* __restrict__ out_attn) {
    __shared__ float s_wx[TT];
    __shared__ float s_red[256];
    int b = blockIdx.x;
    int n = threadIdx.x;
    if (n < TT) s_wx[n] = attn_w[2 * HH + n];
    __syncthreads();

    const float* xb = x + (size_t)b * TT * NN + n;
    float feat = attn_b[0];
#pragma unroll 8
    for (int t = 0; t < TT; t++) feat = fmaf(xb[(size_t)t * NN], s_wx[t], feat);

    s_red[n] = feat;
    __syncthreads();
#pragma unroll
    for (int s = 128; s > 0; s >>= 1) {
        if (n < s) s_red[n] = fmaxf(s_red[n], s_red[n + s]);
        __syncthreads();
    }
    float m = s_red[0];
    __syncthreads();
    float e = expf(feat - m);
    s_red[n] = e;
    __syncthreads();
#pragma unroll
    for (int s = 128; s > 0; s >>= 1) {
        if (n < s) s_red[n] += s_red[n + s];
        __syncthreads();
    }
    float a = e / s_red[0];

    g_a[b * NN + n] = a;

    float* ob = out_attn + (size_t)b * TT * NN + n;
#pragma unroll 8
    for (int t = 0; t < TT; t++) ob[(size_t)t * NN] = a;
}

// ---------------------------------------------------------------------------
// xproj via wmma bf16 3-pass split (HMMA path; fp32 accumulate).
// Grid (4 jt, 1024 b). CTA tile 128(t) x 128(j), K' = 768.
// A (a*x split) built once in smem; B streamed in 64-k' chunks,
// register-prefetched, double-buffered smem, one sync per chunk.
// ---------------------------------------------------------------------------
#define SMX_A  0
#define SMX_B  (128 * AP * 2)                  // 135168
#define SMX_SA (SMX_B + 2 * 128 * BP * 2)      // 171,  135168+36864=172032
#define XP_SMEM (SMX_SA + NN * 4)              // 173056

__global__ __launch_bounds__(256, 1)
void xproj_wmma_kernel(const float* __restrict__ x, float* __restrict__ xp) {
    extern __shared__ char smem[];
    __nv_bfloat16* As = (__nv_bfloat16*)(smem + SMX_A);   // [128][AP]
    __nv_bfloat16* Bs = (__nv_bfloat16*)(smem + SMX_B);   // [2][128][BP]
    float* s_a = (float*)(smem + SMX_SA);

    int jt = blockIdx.x, b = blockIdx.y;
    int tid = threadIdx.x;
    int wid = tid >> 5;
    const float* xb = x + (size_t)b * TT * NN;

    if (tid < 64) ((float4*)s_a)[tid] = ((const float4*)(g_a + b * NN))[tid];
    __syncthreads();

    // ---- build A: hi at [t][k], lo at [t][256+k] ----
#pragma unroll
    for (int it = 0; it < 16; it++) {
        int seg = tid + 256 * it;          // 4096 segs of 8 k
        int t = seg >> 5;
        int k8 = (seg & 31) * 8;
        float4 x0 = *(const float4*)&xb[t * NN + k8];
        float4 x1 = *(const float4*)&xb[t * NN + k8 + 4];
        float4 a0 = *(const float4*)&s_a[k8];
        float4 a1 = *(const float4*)&s_a[k8 + 4];
        float v[8] = {x0.x * a0.x, x0.y * a0.y, x0.z * a0.z, x0.w * a0.w,
                      x1.x * a1.x, x1.y * a1.y, x1.z * a1.z, x1.w * a1.w};
        u32 hw[4], lw[4];
#pragma unroll
        for (int p = 0; p < 4; p++) {
            __nv_bfloat16 h0 = __float2bfloat16_rn(v[2 * p]);
            __nv_bfloat16 h1 = __float2bfloat16_rn(v[2 * p + 1]);
            __nv_bfloat16 l0 = __float2bfloat16_rn(v[2 * p] - __bfloat162float(h0));
            __nv_bfloat16 l1 = __float2bfloat16_rn(v[2 * p + 1] - __bfloat162float(h1));
            __nv_bfloat162 hp = __halves2bfloat162(h0, h1);
            __nv_bfloat162 lp = __halves2bfloat162(l0, l1);
            hw[p] = *(u32*)&hp; lw[p] = *(u32*)&lp;
        }
        *(uint4*)&As[t * AP + k8]       = make_uint4(hw[0], hw[1], hw[2], hw[3]);
        *(uint4*)&As[t * AP + 256 + k8] = make_uint4(lw[0], lw[1], lw[2], lw[3]);
    }

    // ---- prefetch B chunk 0 into registers ----
    uint4 rb[4];
#pragma unroll
    for (int it = 0; it < 4; it++) {
        int seg = tid + 256 * it;
        int j = seg >> 3, kl8 = (seg & 7) * 8;
        rb[it] = *(const uint4*)&g_wcat[(size_t)(jt * 128 + j) * KP + kl8];
    }

    // ---- accumulators: warp tile 32(m) x 64(n); warps 4x2 ----
    int m0 = (wid >> 1) * 32;
    int n0 = (wid & 1) * 64;
    wmma::fragment<wmma::accumulator, 16, 16, 16, float> acc[2][4];
#pragma unroll
    for (int i = 0; i < 2; i++)
#pragma unroll
        for (int nn = 0; nn < 4; nn++) wmma::fill_fragment(acc[i][nn], 0.0f);

    __syncthreads();   // As visible

    for (int c = 0; c < 12; c++) {
        __nv_bfloat16* Bc = Bs + (c & 1) * 128 * BP;
        // store prefetched chunk
#pragma unroll
        for (int it = 0; it < 4; it++) {
            int seg = tid + 256 * it;
            int j = seg >> 3, kl8 = (seg & 7) * 8;
            *(uint4*)&Bc[j * BP + kl8] = rb[it];
        }
        __syncthreads();

        if (c < 11) {
            int kb = (c + 1) * 64;
#pragma unroll
            for (int it = 0; it < 4; it++) {
                int seg = tid + 256 * it;
                int j = seg >> 3, kl8 = (seg & 7) * 8;
                rb[it] = *(const uint4*)&g_wcat[(size_t)(jt * 128 + j) * KP + kb + kl8];
            }
        }

        int kprime = c * 64;
        int a_off = (kprime < 512) ? (kprime & 255) : ((kprime & 255) + 256);

#pragma unroll
        for (int ks = 0; ks < 4; ks++) {
            wmma::fragment<wmma::matrix_a, 16, 16, 16, __nv_bfloat16, wmma::row_major> af[2];
#pragma unroll
            for (int i = 0; i < 2; i++)
                wmma::load_matrix_sync(af[i], &As[(m0 + i * 16) * AP + a_off + ks * 16], AP);
#pragma unroll
            for (int nn = 0; nn < 4; nn++) {
                wmma::fragment<wmma::matrix_b, 16, 16, 16, __nv_bfloat16, wmma::col_major> bf;
                wmma::load_matrix_sync(bf, &Bc[(n0 + nn * 16) * BP + ks * 16], BP);
                wmma::mma_sync(acc[0][nn], af[0], bf, acc[0][nn]);
                wmma::mma_sync(acc[1][nn], af[1], bf, acc[1][nn]);
            }
        }
    }

    // ---- epilogue: direct store to xproj ----
#pragma unroll
    for (int i = 0; i < 2; i++)
#pragma unroll
        for (int nn = 0; nn < 4; nn++)
            wmma::store_matrix_sync(
                xp + ((size_t)b * TT + m0 + i * 16) * GG + jt * 128 + n0 + nn * 16,
                acc[i][nn], GG, wmma::mem_row_major);
}

// ---------------------------------------------------------------------------
// Recurrent LSTM — unchanged (620 us config).
// ---------------------------------------------------------------------------
__global__ __launch_bounds__(512, 1)
void lstm_kernel(const float* __restrict__ xp,
                 const float* __restrict__ h0,
                 const float* __restrict__ c0,
                 float* __restrict__ out_enc) {
    extern __shared__ char smem_raw[];
    float4* ws  = (float4*)smem_raw;
    float*  s_h = (float*)(smem_raw + SM_K4 * GG * 16);
    float*  s_c = s_h + BM * HH;
    float*  s_g = s_c + BM * HH;

    int tid = threadIdx.x;
    int b0 = blockIdx.x * BM;
    int j = tid;

    for (int i = tid; i < SM_K4 * GG; i += 512) ws[i] = g_whh4[i];

    ulonglong2 wt[8];
#pragma unroll
    for (int q = 0; q < 8; q++)
        wt[q] = *(const ulonglong2*)&g_whh4[(SM_K4 + q) * GG + j];

    for (int i = tid; i < BM * HH; i += 512) {
        int r = i >> 7, k = i & (HH - 1);
        int b = b0 + r;
        float hv = 0.f, cv = 0.f;
        if (b < BB) { hv = h0[(size_t)b * HH + k]; cv = c0[(size_t)b * HH + k]; }
        s_h[i] = hv; s_c[i] = cv;
    }
    float bias = g_bias[j];
    __syncthreads();

    const float* xrow[BM];
#pragma unroll
    for (int r = 0; r < BM; r++) {
        int b = b0 + r; if (b > BB - 1) b = BB - 1;
        xrow[r] = xp + (size_t)b * TT * GG + j;
    }

    const float4* wsj = ws + j;
    const int lin = tid * 2;
    const int er = lin >> 7, ek = lin & (HH - 1);
    const bool eact = lin < BM * HH;
    const bool ewr  = eact && (b0 + er < BB);

    for (int t = 0; t < TT; t++) {
        float xpv[BM];
#pragma unroll
        for (int r = 0; r < BM; r++) xpv[r] = xrow[r][(size_t)t * GG];

        ull acc[BM];
#pragma unroll
        for (int r = 0; r < BM; r++) acc[r] = 0ULL;

#pragma unroll
        for (int k4 = 0; k4 < SM_K4; k4++) {
            ulonglong2 wp = *(const ulonglong2*)&wsj[k4 * GG];
#pragma unroll
            for (int r = 0; r < BM; r++) {
                ulonglong2 hp = *(const ulonglong2*)&s_h[r * HH + k4 * 4];
                fma2(acc[r], hp.x, wp.x);
                fma2(acc[r], hp.y, wp.y);
            }
        }
#pragma unroll
        for (int q = 0; q < 8; q++) {
#pragma unroll
            for (int r = 0; r < BM; r++) {
                ulonglong2 hp = *(const ulonglong2*)&s_h[r * HH + (SM_K4 + q) * 4];
                fma2(acc[r], hp.x, wt[q].x);
                fma2(acc[r], hp.y, wt[q].y);
            }
        }

#pragma unroll
        for (int r = 0; r < BM; r++) {
            float2 p = unpack2(acc[r]);
            s_g[r * GG + j] = p.x + p.y + bias + xpv[r];
        }
        __syncthreads();

        if (eact) {
            float2 gi = *(const float2*)&s_g[er * GG + ek];
            float2 gf = *(const float2*)&s_g[er * GG + HH + ek];
            float2 gg = *(const float2*)&s_g[er * GG + 2 * HH + ek];
            float2 go = *(const float2*)&s_g[er * GG + 3 * HH + ek];
            float2 cc = *(const float2*)&s_c[er * HH + ek];

            float i0 = fsig(gi.x), i1 = fsig(gi.y);
            float f0 = fsig(gf.x), f1 = fsig(gf.y);
            float g0 = ftanh(gg.x), g1 = ftanh(gg.y);
            float o0 = fsig(go.x), o1 = fsig(go.y);

            float c0n = fmaf(f0, cc.x, i0 * g0);
            float c1n = fmaf(f1, cc.y, i1 * g1);
            float h0n = o0 * ftanh(c0n);
            float h1n = o1 * ftanh(c1n);

            *(float2*)&s_c[er * HH + ek] = make_float2(c0n, c1n);
            *(float2*)&s_h[er * HH + ek] = make_float2(h0n, h1n);
            if (ewr)
                *(float2*)(out_enc + ((size_t)(b0 + er) * TT + t) * HH + ek) =
                    make_float2(h0n, h1n);
        }
        __syncthreads();
    }
}

// ---------------------------------------------------------------------------
// Launch
// ---------------------------------------------------------------------------
extern "C" void kernel_launch(void* const* d_in, const int* in_sizes, int n_in,
                              void* d_out, int out_size) {
    const float* x      = (const float*)d_in[0];
    const float* attn_w = (const float*)d_in[1];
    const float* attn_b = (const float*)d_in[2];
    const float* w_ih   = (const float*)d_in[3];
    const float* w_hh   = (const float*)d_in[4];
    const float* b_ih   = (const float*)d_in[5];
    const float* b_hh   = (const float*)d_in[6];
    const float* h0     = (const float*)d_in[7];
    const float* c0     = (const float*)d_in[8];

    float* out      = (float*)d_out;
    float* out_attn = out;
    float* out_enc  = out + (size_t)BB * TT * NN;

    float* xproj;
    cudaGetSymbolAddress((void**)&xproj, g_xproj);

    int lstm_smem = SM_K4 * GG * 16 + BM * HH * 4 * 2 + BM * GG * 4;
    cudaFuncSetAttribute(lstm_kernel,
                         cudaFuncAttributeMaxDynamicSharedMemorySize, lstm_smem);
    cudaFuncSetAttribute(xproj_wmma_kernel,
                         cudaFuncAttributeMaxDynamicSharedMemorySize, XP_SMEM);

    setup_kernel<<<192, 256>>>(w_ih, w_hh, b_ih, b_hh);
    attn_kernel<<<BB, 256>>>(x, attn_w, attn_b, out_attn);
    xproj_wmma_kernel<<<dim3(4, BB), 256, XP_SMEM>>>(x, xproj);
    lstm_kernel<<<NBLK, 512, lstm_smem>>>(xproj, h0, c0, out_enc);
}

// round 8
// speedup vs baseline: 3.0307x; 1.1709x over previous
#include <cuda_runtime.h>
#include <cuda_bf16.h>
#include <mma.h>
#include <math.h>

using namespace nvcuda;

#define BB 1024
#define TT 128
#define NN 256
#define HH 128
#define GG 512
#define BM 7
#define NBLK 147
#define SM_K4 24        // k4 groups (4 k each) of w_hh^T cached in smem (k<96)
#define KP 768          // concatenated K' = 3*256 (hi|lo|hi)
#define AP 528          // A smem row pitch (bf16 elems)
#define BP 72           // B smem column pitch (bf16 elems)

typedef unsigned long long ull;
typedef unsigned int u32;

// ---------------- scratch ----------------------------------------------------
__device__ float  g_a[BB * NN];
__device__ float4 g_whh4[32 * GG];
__device__ float  g_bias[GG];
__device__ float  g_xproj[(size_t)BB * TT * GG];
__device__ __nv_bfloat16 g_wcat[GG * KP];   // [j][k'] : k'<256 hi, <512 lo, <768 hi

// ---------------- f32x2 helpers ----------------------------------------------
__device__ __forceinline__ void fma2(ull& d, ull a, ull b) {
    asm("fma.rn.f32x2 %0, %1, %2, %0;" : "+l"(d) : "l"(a), "l"(b));
}
__device__ __forceinline__ float2 unpack2(ull v) {
    float2 f; asm("mov.b64 {%0,%1}, %2;" : "=f"(f.x), "=f"(f.y) : "l"(v)); return f;
}
__device__ __forceinline__ float fsig(float x) {
    float e = __expf(-x); return __fdividef(1.0f, 1.0f + e);
}
__device__ __forceinline__ float ftanh(float x) {
    float e = __expf(2.0f * x); return 1.0f - __fdividef(2.0f, e + 1.0f);
}

// ---------------------------------------------------------------------------
// Setup: lstm weight interleave + bias fold + bf16 split-concat of w_ih.
// ---------------------------------------------------------------------------
__global__ void setup_kernel(const float* __restrict__ w_ih,
                             const float* __restrict__ w_hh,
                             const float* __restrict__ b_ih,
                             const float* __restrict__ b_hh) {
    int idx = blockIdx.x * blockDim.x + threadIdx.x;
    int stride = gridDim.x * blockDim.x;
    if (idx < GG) g_bias[idx] = b_ih[idx] + b_hh[idx];
    for (int i = idx; i < 32 * GG; i += stride) {
        int k4 = i >> 9, j = i & (GG - 1);
        const float* wr = w_hh + j * HH + 4 * k4;
        g_whh4[i] = make_float4(wr[0], wr[1], wr[2], wr[3]);
    }
    for (int i = idx; i < GG * KP; i += stride) {
        int j = i / KP, kp = i % KP;
        int k = kp & 255;
        float v = w_ih[j * NN + k];
        __nv_bfloat16 hi = __float2bfloat16_rn(v);
        __nv_bfloat16 outv;
        if (kp < 256)       outv = hi;
        else if (kp < 512)  outv = __float2bfloat16_rn(v - __bfloat162float(hi));
        else                outv = hi;
        g_wcat[i] = outv;
    }
}

// ---------------------------------------------------------------------------
// Attention (time-invariant softmax) — unchanged.
// ---------------------------------------------------------------------------
__global__ __launch_bounds__(256)
void attn_kernel(const float* __restrict__ x,
                 const float* __restrict__ attn_w,
                 const float* __restrict__ attn_b,
                 float* __restrict__ out_attn) {
    __shared__ float s_wx[TT];
    __shared__ float s_red[256];
    int b = blockIdx.x;
    int n = threadIdx.x;
    if (n < TT) s_wx[n] = attn_w[2 * HH + n];
    __syncthreads();

    const float* xb = x + (size_t)b * TT * NN + n;
    float feat = attn_b[0];
#pragma unroll 8
    for (int t = 0; t < TT; t++) feat = fmaf(xb[(size_t)t * NN], s_wx[t], feat);

    s_red[n] = feat;
    __syncthreads();
#pragma unroll
    for (int s = 128; s > 0; s >>= 1) {
        if (n < s) s_red[n] = fmaxf(s_red[n], s_red[n + s]);
        __syncthreads();
    }
    float m = s_red[0];
    __syncthreads();
    float e = expf(feat - m);
    s_red[n] = e;
    __syncthreads();
#pragma unroll
    for (int s = 128; s > 0; s >>= 1) {
        if (n < s) s_red[n] += s_red[n + s];
        __syncthreads();
    }
    float a = e / s_red[0];

    g_a[b * NN + n] = a;

    float* ob = out_attn + (size_t)b * TT * NN + n;
#pragma unroll 8
    for (int t = 0; t < TT; t++) ob[(size_t)t * NN] = a;
}

// ---------------------------------------------------------------------------
// xproj via wmma bf16 3-pass split — unchanged from round 6 (working, ~440us).
// ---------------------------------------------------------------------------
#define SMX_A  0
#define SMX_B  (128 * AP * 2)
#define SMX_SA (SMX_B + 2 * 128 * BP * 2)
#define XP_SMEM (SMX_SA + NN * 4)

__global__ __launch_bounds__(256, 1)
void xproj_wmma_kernel(const float* __restrict__ x, float* __restrict__ xp) {
    extern __shared__ char smem[];
    __nv_bfloat16* As = (__nv_bfloat16*)(smem + SMX_A);
    __nv_bfloat16* Bs = (__nv_bfloat16*)(smem + SMX_B);
    float* s_a = (float*)(smem + SMX_SA);

    int jt = blockIdx.x, b = blockIdx.y;
    int tid = threadIdx.x;
    int wid = tid >> 5;
    const float* xb = x + (size_t)b * TT * NN;

    if (tid < 64) ((float4*)s_a)[tid] = ((const float4*)(g_a + b * NN))[tid];
    __syncthreads();

#pragma unroll
    for (int it = 0; it < 16; it++) {
        int seg = tid + 256 * it;
        int t = seg >> 5;
        int k8 = (seg & 31) * 8;
        float4 x0 = *(const float4*)&xb[t * NN + k8];
        float4 x1 = *(const float4*)&xb[t * NN + k8 + 4];
        float4 a0 = *(const float4*)&s_a[k8];
        float4 a1 = *(const float4*)&s_a[k8 + 4];
        float v[8] = {x0.x * a0.x, x0.y * a0.y, x0.z * a0.z, x0.w * a0.w,
                      x1.x * a1.x, x1.y * a1.y, x1.z * a1.z, x1.w * a1.w};
        u32 hw[4], lw[4];
#pragma unroll
        for (int p = 0; p < 4; p++) {
            __nv_bfloat16 h0 = __float2bfloat16_rn(v[2 * p]);
            __nv_bfloat16 h1 = __float2bfloat16_rn(v[2 * p + 1]);
            __nv_bfloat16 l0 = __float2bfloat16_rn(v[2 * p] - __bfloat162float(h0));
            __nv_bfloat16 l1 = __float2bfloat16_rn(v[2 * p + 1] - __bfloat162float(h1));
            __nv_bfloat162 hp = __halves2bfloat162(h0, h1);
            __nv_bfloat162 lp = __halves2bfloat162(l0, l1);
            hw[p] = *(u32*)&hp; lw[p] = *(u32*)&lp;
        }
        *(uint4*)&As[t * AP + k8]       = make_uint4(hw[0], hw[1], hw[2], hw[3]);
        *(uint4*)&As[t * AP + 256 + k8] = make_uint4(lw[0], lw[1], lw[2], lw[3]);
    }

    uint4 rb[4];
#pragma unroll
    for (int it = 0; it < 4; it++) {
        int seg = tid + 256 * it;
        int j = seg >> 3, kl8 = (seg & 7) * 8;
        rb[it] = *(const uint4*)&g_wcat[(size_t)(jt * 128 + j) * KP + kl8];
    }

    int m0 = (wid >> 1) * 32;
    int n0 = (wid & 1) * 64;
    wmma::fragment<wmma::accumulator, 16, 16, 16, float> acc[2][4];
#pragma unroll
    for (int i = 0; i < 2; i++)
#pragma unroll
        for (int nn = 0; nn < 4; nn++) wmma::fill_fragment(acc[i][nn], 0.0f);

    __syncthreads();

    for (int c = 0; c < 12; c++) {
        __nv_bfloat16* Bc = Bs + (c & 1) * 128 * BP;
#pragma unroll
        for (int it = 0; it < 4; it++) {
            int seg = tid + 256 * it;
            int j = seg >> 3, kl8 = (seg & 7) * 8;
            *(uint4*)&Bc[j * BP + kl8] = rb[it];
        }
        __syncthreads();

        if (c < 11) {
            int kb = (c + 1) * 64;
#pragma unroll
            for (int it = 0; it < 4; it++) {
                int seg = tid + 256 * it;
                int j = seg >> 3, kl8 = (seg & 7) * 8;
                rb[it] = *(const uint4*)&g_wcat[(size_t)(jt * 128 + j) * KP + kb + kl8];
            }
        }

        int kprime = c * 64;
        int a_off = (kprime < 512) ? (kprime & 255) : ((kprime & 255) + 256);

#pragma unroll
        for (int ks = 0; ks < 4; ks++) {
            wmma::fragment<wmma::matrix_a, 16, 16, 16, __nv_bfloat16, wmma::row_major> af[2];
#pragma unroll
            for (int i = 0; i < 2; i++)
                wmma::load_matrix_sync(af[i], &As[(m0 + i * 16) * AP + a_off + ks * 16], AP);
#pragma unroll
            for (int nn = 0; nn < 4; nn++) {
                wmma::fragment<wmma::matrix_b, 16, 16, 16, __nv_bfloat16, wmma::col_major> bf;
                wmma::load_matrix_sync(bf, &Bc[(n0 + nn * 16) * BP + ks * 16], BP);
                wmma::mma_sync(acc[0][nn], af[0], bf, acc[0][nn]);
                wmma::mma_sync(acc[1][nn], af[1], bf, acc[1][nn]);
            }
        }
    }

#pragma unroll
    for (int i = 0; i < 2; i++)
#pragma unroll
        for (int nn = 0; nn < 4; nn++)
            wmma::store_matrix_sync(
                xp + ((size_t)b * TT + m0 + i * 16) * GG + jt * 128 + n0 + nn * 16,
                acc[i][nn], GG, wmma::mem_row_major);
}

// ---------------------------------------------------------------------------
// Recurrent LSTM, v3: 256 threads, 2 gate columns per thread (j, j+256).
// Each h-broadcast LDS feeds 4 FFMA2 (2x the old intensity) -> per-SM
// smem wavefronts/step drop ~5120 -> ~3400. All weights on-chip:
// k<96 in smem (one LDS.128 per (k4, col)), k>=96 in registers (both cols).
// ---------------------------------------------------------------------------
__global__ __launch_bounds__(256, 1)
void lstm_kernel(const float* __restrict__ xp,
                 const float* __restrict__ h0,
                 const float* __restrict__ c0,
                 float* __restrict__ out_enc) {
    extern __shared__ char smem_raw[];
    float4* ws  = (float4*)smem_raw;                     // [SM_K4][GG]
    float*  s_h = (float*)(smem_raw + SM_K4 * GG * 16);  // [BM][HH]
    float*  s_c = s_h + BM * HH;                         // [BM][HH]
    float*  s_g = s_c + BM * HH;                         // [BM][GG]

    int tid = threadIdx.x;
    int b0 = blockIdx.x * BM;
    int j0 = tid, j1 = tid + 256;

    for (int i = tid; i < SM_K4 * GG; i += 256) ws[i] = g_whh4[i];

    // tail weights (k = 96..127) in registers for BOTH columns
    ulonglong2 wt0[8], wt1[8];
#pragma unroll
    for (int q = 0; q < 8; q++) {
        wt0[q] = *(const ulonglong2*)&g_whh4[(SM_K4 + q) * GG + j0];
        wt1[q] = *(const ulonglong2*)&g_whh4[(SM_K4 + q) * GG + j1];
    }

    for (int i = tid; i < BM * HH; i += 256) {
        int r = i >> 7, k = i & (HH - 1);
        int b = b0 + r;
        float hv = 0.f, cv = 0.f;
        if (b < BB) { hv = h0[(size_t)b * HH + k]; cv = c0[(size_t)b * HH + k]; }
        s_h[i] = hv; s_c[i] = cv;
    }
    float bias0 = g_bias[j0], bias1 = g_bias[j1];
    __syncthreads();

    const float* xrow[BM];
#pragma unroll
    for (int r = 0; r < BM; r++) {
        int b = b0 + r; if (b > BB - 1) b = BB - 1;
        xrow[r] = xp + (size_t)b * TT * GG;
    }

    const float4* wsj0 = ws + j0;
    const float4* wsj1 = ws + j1;
    const int lin = tid * 4;                       // epilogue: 4 cells, same row
    const int er = lin >> 7, ek = lin & (HH - 1);
    const bool eact = lin < BM * HH;
    const bool ewr  = eact && (b0 + er < BB);

    for (int t = 0; t < TT; t++) {
        // prefetch xproj for this step (consumed after the matvec)
        float xpv0[BM], xpv1[BM];
#pragma unroll
        for (int r = 0; r < BM; r++) {
            xpv0[r] = xrow[r][(size_t)t * GG + j0];
            xpv1[r] = xrow[r][(size_t)t * GG + j1];
        }

        ull acc0[BM], acc1[BM];
#pragma unroll
        for (int r = 0; r < BM; r++) { acc0[r] = 0ULL; acc1[r] = 0ULL; }

        // register-resident tail first (k = 96..127): zero smem weight traffic
#pragma unroll
        for (int q = 0; q < 8; q++) {
#pragma unroll
            for (int r = 0; r < BM; r++) {
                ulonglong2 hp = *(const ulonglong2*)&s_h[r * HH + (SM_K4 + q) * 4];
                fma2(acc0[r], hp.x, wt0[q].x); fma2(acc0[r], hp.y, wt0[q].y);
                fma2(acc1[r], hp.x, wt1[q].x); fma2(acc1[r], hp.y, wt1[q].y);
            }
        }
        // smem-resident body (k = 0..95)
#pragma unroll
        for (int k4 = 0; k4 < SM_K4; k4++) {
            ulonglong2 w0 = *(const ulonglong2*)&wsj0[k4 * GG];
            ulonglong2 w1 = *(const ulonglong2*)&wsj1[k4 * GG];
#pragma unroll
            for (int r = 0; r < BM; r++) {
                ulonglong2 hp = *(const ulonglong2*)&s_h[r * HH + k4 * 4];
                fma2(acc0[r], hp.x, w0.x); fma2(acc0[r], hp.y, w0.y);
                fma2(acc1[r], hp.x, w1.x); fma2(acc1[r], hp.y, w1.y);
            }
        }

#pragma unroll
        for (int r = 0; r < BM; r++) {
            float2 p0 = unpack2(acc0[r]);
            float2 p1 = unpack2(acc1[r]);
            s_g[r * GG + j0] = p0.x + p0.y + bias0 + xpv0[r];
            s_g[r * GG + j1] = p1.x + p1.y + bias1 + xpv1[r];
        }
        __syncthreads();

        // gate activations + state update: thread owns cells (er, ek..ek+3)
        if (eact) {
            float4 gi = *(const float4*)&s_g[er * GG + ek];
            float4 gf = *(const float4*)&s_g[er * GG + HH + ek];
            float4 gg = *(const float4*)&s_g[er * GG + 2 * HH + ek];
            float4 go = *(const float4*)&s_g[er * GG + 3 * HH + ek];
            float4 cc = *(const float4*)&s_c[er * HH + ek];

            float gI[4] = {gi.x, gi.y, gi.z, gi.w};
            float gF[4] = {gf.x, gf.y, gf.z, gf.w};
            float gGv[4] = {gg.x, gg.y, gg.z, gg.w};
            float gO[4] = {go.x, go.y, go.z, go.w};
            float cC[4] = {cc.x, cc.y, cc.z, cc.w};
            float hn[4], cn[4];
#pragma unroll
            for (int l = 0; l < 4; l++) {
                float iv = fsig(gI[l]);
                float fv = fsig(gF[l]);
                float gv = ftanh(gGv[l]);
                float ov = fsig(gO[l]);
                cn[l] = fmaf(fv, cC[l], iv * gv);
                hn[l] = ov * ftanh(cn[l]);
            }
            *(float4*)&s_c[er * HH + ek] = make_float4(cn[0], cn[1], cn[2], cn[3]);
            *(float4*)&s_h[er * HH + ek] = make_float4(hn[0], hn[1], hn[2], hn[3]);
            if (ewr)
                *(float4*)(out_enc + ((size_t)(b0 + er) * TT + t) * HH + ek) =
                    make_float4(hn[0], hn[1], hn[2], hn[3]);
        }
        __syncthreads();
    }
}

// ---------------------------------------------------------------------------
// Launch
// ---------------------------------------------------------------------------
extern "C" void kernel_launch(void* const* d_in, const int* in_sizes, int n_in,
                              void* d_out, int out_size) {
    const float* x      = (const float*)d_in[0];
    const float* attn_w = (const float*)d_in[1];
    const float* attn_b = (const float*)d_in[2];
    const float* w_ih   = (const float*)d_in[3];
    const float* w_hh   = (const float*)d_in[4];
    const float* b_ih   = (const float*)d_in[5];
    const float* b_hh   = (const float*)d_in[6];
    const float* h0     = (const float*)d_in[7];
    const float* c0     = (const float*)d_in[8];

    float* out      = (float*)d_out;
    float* out_attn = out;
    float* out_enc  = out + (size_t)BB * TT * NN;

    float* xproj;
    cudaGetSymbolAddress((void**)&xproj, g_xproj);

    int lstm_smem = SM_K4 * GG * 16 + BM * HH * 4 * 2 + BM * GG * 4;  // 218112
    cudaFuncSetAttribute(lstm_kernel,
                         cudaFuncAttributeMaxDynamicSharedMemorySize, lstm_smem);
    cudaFuncSetAttribute(xproj_wmma_kernel,
                         cudaFuncAttributeMaxDynamicSharedMemorySize, XP_SMEM);

    setup_kernel<<<192, 256>>>(w_ih, w_hh, b_ih, b_hh);
    attn_kernel<<<BB, 256>>>(x, attn_w, attn_b, out_attn);
    xproj_wmma_kernel<<<dim3(4, BB), 256, XP_SMEM>>>(x, xproj);
    lstm_kernel<<<NBLK, 256, lstm_smem>>>(xproj, h0, c0, out_enc);
}